// round 3
// baseline (speedup 1.0000x reference)
#include <cuda_runtime.h>

#define NN 50000
#define EE 800000
#define FIN 128
#define HH 64
#define H2 128
#define MSG_EPS 1e-7f

// Scratch (device globals; no allocation allowed)
__device__ __align__(16) float g_x0[NN * HH];       // encoder out / conv1 in
__device__ __align__(16) float g_x1[NN * HH];       // conv1 out / conv2 in
__device__ __align__(16) float g_x2[NN * HH];       // conv2 out (pre-LN h)
__device__ __align__(16) float g_acc[NN * 2 * HH];  // [n][0:64]=denom, [n][64:128]=numer

__global__ void zero_acc_kernel() {
    int i = blockIdx.x * blockDim.x + threadIdx.x;
    const int total = NN * 2 * HH / 4;
    float4 z = make_float4(0.f, 0.f, 0.f, 0.f);
    for (; i < total; i += gridDim.x * blockDim.x)
        ((float4*)g_acc)[i] = z;
}

// ---------------------------------------------------------------------------
// Encoder: x[N,128] @ W[128,64] + b  -> out[N,64]. W resident in smem.
__global__ __launch_bounds__(256) void encoder_kernel(
    const float* __restrict__ x, const float* __restrict__ W,
    const float* __restrict__ b, float* __restrict__ out) {
    __shared__ float Ws[FIN * HH];  // 32 KB
    __shared__ float xs[4 * FIN];   // 2 KB
    int t = threadIdx.x;
    for (int i = t; i < FIN * HH; i += 256) Ws[i] = W[i];
    float bh = b[t & 63];
    __syncthreads();
    for (int n0 = blockIdx.x * 4; n0 < NN; n0 += gridDim.x * 4) {
        for (int i = t; i < 4 * FIN; i += 256)
            xs[i] = x[(size_t)n0 * FIN + i];
        __syncthreads();
        int node = t >> 6, h = t & 63;
        float acc = bh;
        const float* xr = &xs[node * FIN];
#pragma unroll
        for (int k = 0; k < FIN; k++)
            acc = fmaf(xr[k], Ws[k * HH + h], acc);
        out[(size_t)(n0 + node) * HH + h] = acc;
        __syncthreads();
    }
}

// ---------------------------------------------------------------------------
// Fused edge pass: m = relu(x[src])+eps ; ex = exp(m*t) ;
// red denom[dst] += ex ; red numer[dst] += m*ex.
// (seg_max eliminated: softmax is shift-invariant; logits here are O(1))
// Thread = (edge, 4-channel group). 16 threads cover one edge's 64 channels.
// edge_index is int32 (JAX default x64-disabled demotes int64 -> int32).
__device__ __forceinline__ void red_add_v4(float* p, float a, float b, float c,
                                           float d) {
    asm volatile("red.global.add.v4.f32 [%0], {%1, %2, %3, %4};" ::"l"(p),
                 "f"(a), "f"(b), "f"(c), "f"(d)
                 : "memory");
}

__global__ __launch_bounds__(256) void edge_pass_kernel(
    const float* __restrict__ xin, const int* __restrict__ ei,
    const float* __restrict__ tp) {
    int idx = blockIdx.x * blockDim.x + threadIdx.x;
    int e = idx >> 4;
    if (e >= EE) return;
    int cg = idx & 15;
    float t = __ldg(tp);
    int s = __ldg(ei + e);
    int d = __ldg(ei + EE + e);
    float4 xv = *(const float4*)(xin + (size_t)s * HH + cg * 4);
    float m0 = fmaxf(xv.x, 0.f) + MSG_EPS;
    float m1 = fmaxf(xv.y, 0.f) + MSG_EPS;
    float m2 = fmaxf(xv.z, 0.f) + MSG_EPS;
    float m3 = fmaxf(xv.w, 0.f) + MSG_EPS;
    float e0 = __expf(m0 * t);
    float e1 = __expf(m1 * t);
    float e2 = __expf(m2 * t);
    float e3 = __expf(m3 * t);
    float* base = g_acc + (size_t)d * (2 * HH);
    red_add_v4(base + cg * 4, e0, e1, e2, e3);
    red_add_v4(base + HH + cg * 4, m0 * e0, m1 * e1, m2 * e2, m3 * e3);
}

// ---------------------------------------------------------------------------
// Fused node pass: row = numer/(denom+1e-16) + x_in ;
// h1 = relu(LN(row@W1+b1)) ; out = h1@W2 + b2.
// W1 (64x128) + W2 (128x64) in 64 KB dynamic smem; block loops over nodes.
extern __shared__ float smem_dyn[];
__global__ __launch_bounds__(128) void node_mlp_kernel(
    const float* __restrict__ xin, float* __restrict__ xout,
    const float* __restrict__ W1, const float* __restrict__ b1,
    const float* __restrict__ g1, const float* __restrict__ be1,
    const float* __restrict__ W2, const float* __restrict__ b2) {
    float* W1s = smem_dyn;            // [64][128]
    float* W2s = smem_dyn + HH * H2;  // [128][64]
    __shared__ float b1s[H2], g1s[H2], be1s[H2], b2s[HH];
    __shared__ float row[HH], h1s[H2], outp[HH];
    __shared__ float redA[4], redB[4];
    int t = threadIdx.x;
    for (int i = t; i < HH * H2; i += 128) {
        W1s[i] = W1[i];
        W2s[i] = W2[i];
    }
    b1s[t] = b1[t];
    g1s[t] = g1[t];
    be1s[t] = be1[t];
    if (t < HH) b2s[t] = b2[t];
    __syncthreads();
    int w = t >> 5, lane = t & 31;
    for (int n = blockIdx.x; n < NN; n += gridDim.x) {
        if (t < HH) {
            float den = g_acc[(size_t)n * (2 * HH) + t];
            float num = g_acc[(size_t)n * (2 * HH) + HH + t];
            row[t] = num / (den + 1e-16f) + xin[(size_t)n * HH + t];
        }
        __syncthreads();
        // Linear 64 -> 128 (thread t computes output channel t)
        float v = b1s[t];
#pragma unroll
        for (int i = 0; i < HH; i++)
            v = fmaf(row[i], W1s[i * H2 + t], v);
        // LayerNorm over 128
        float s1 = v, s2 = v * v;
#pragma unroll
        for (int o = 16; o; o >>= 1) {
            s1 += __shfl_xor_sync(0xffffffffu, s1, o);
            s2 += __shfl_xor_sync(0xffffffffu, s2, o);
        }
        if (lane == 0) { redA[w] = s1; redB[w] = s2; }
        __syncthreads();
        float S1 = redA[0] + redA[1] + redA[2] + redA[3];
        float S2 = redB[0] + redB[1] + redB[2] + redB[3];
        float mu = S1 * (1.f / H2);
        float var = S2 * (1.f / H2) - mu * mu;
        float hn = (v - mu) * rsqrtf(var + 1e-5f) * g1s[t] + be1s[t];
        hn = fmaxf(hn, 0.f);
        h1s[t] = hn;
        __syncthreads();
        // Linear 128 -> 64 (split the j-sum across two 64-thread halves)
        int c = t & 63, half = t >> 6;
        float acc = 0.f;
#pragma unroll
        for (int j = 0; j < HH; j++)
            acc = fmaf(h1s[half * HH + j], W2s[(half * HH + j) * HH + c], acc);
        if (half == 0) outp[c] = acc;
        __syncthreads();
        if (half == 1) xout[(size_t)n * HH + c] = outp[c] + acc + b2s[c];
    }
}

// ---------------------------------------------------------------------------
// Epilogue: h = relu(LN64(x2)) ; z = relu(LN128([x1, h])) ; out = z @ lin_W + lin_b
// Warp per node, all warp-shuffle reductions.
__global__ __launch_bounds__(256) void final_kernel(
    const float* __restrict__ ln1g, const float* __restrict__ ln1b,
    const float* __restrict__ ng, const float* __restrict__ nb,
    const float* __restrict__ linW, const float* __restrict__ linb,
    float* __restrict__ out) {
    int gw = (blockIdx.x * blockDim.x + threadIdx.x) >> 5;
    int lane = threadIdx.x & 31;
    int nwarps = (gridDim.x * blockDim.x) >> 5;
    for (int n = gw; n < NN; n += nwarps) {
        float a0 = g_x2[(size_t)n * HH + lane];
        float a1 = g_x2[(size_t)n * HH + lane + 32];
        float s1 = a0 + a1, s2 = a0 * a0 + a1 * a1;
#pragma unroll
        for (int o = 16; o; o >>= 1) {
            s1 += __shfl_xor_sync(0xffffffffu, s1, o);
            s2 += __shfl_xor_sync(0xffffffffu, s2, o);
        }
        float mu = s1 * (1.f / 64), var = s2 * (1.f / 64) - mu * mu;
        float rs = rsqrtf(var + 1e-5f);
        float h0 = fmaxf((a0 - mu) * rs * ln1g[lane] + ln1b[lane], 0.f);
        float h1 = fmaxf((a1 - mu) * rs * ln1g[lane + 32] + ln1b[lane + 32], 0.f);
        float c0 = g_x1[(size_t)n * HH + lane];
        float c1 = g_x1[(size_t)n * HH + lane + 32];
        float S1 = c0 + c1 + h0 + h1;
        float S2 = c0 * c0 + c1 * c1 + h0 * h0 + h1 * h1;
#pragma unroll
        for (int o = 16; o; o >>= 1) {
            S1 += __shfl_xor_sync(0xffffffffu, S1, o);
            S2 += __shfl_xor_sync(0xffffffffu, S2, o);
        }
        float mu2 = S1 * (1.f / 128), var2 = S2 * (1.f / 128) - mu2 * mu2;
        float rs2 = rsqrtf(var2 + 1e-5f);
        float z0 = fmaxf((c0 - mu2) * rs2 * ng[lane] + nb[lane], 0.f);
        float z1 = fmaxf((c1 - mu2) * rs2 * ng[lane + 32] + nb[lane + 32], 0.f);
        float z2 = fmaxf((h0 - mu2) * rs2 * ng[64 + lane] + nb[64 + lane], 0.f);
        float z3 = fmaxf((h1 - mu2) * rs2 * ng[96 + lane] + nb[96 + lane], 0.f);
        float dot = z0 * linW[lane] + z1 * linW[lane + 32] +
                    z2 * linW[64 + lane] + z3 * linW[96 + lane];
#pragma unroll
        for (int o = 16; o; o >>= 1)
            dot += __shfl_xor_sync(0xffffffffu, dot, o);
        if (lane == 0) out[n] = dot + linb[0];
    }
}

// ---------------------------------------------------------------------------
extern "C" void kernel_launch(void* const* d_in, const int* in_sizes, int n_in,
                              void* d_out, int out_size) {
    const float* x = (const float*)d_in[0];
    const int* ei = (const int*)d_in[1];  // int32! (JAX x64-disabled)
    const float* encW = (const float*)d_in[2];
    const float* encb = (const float*)d_in[3];
    const float* tp = (const float*)d_in[4];
    const float* W1 = (const float*)d_in[5];
    const float* b1 = (const float*)d_in[6];
    const float* g1 = (const float*)d_in[7];
    const float* be1 = (const float*)d_in[8];
    const float* W2 = (const float*)d_in[9];
    const float* b2 = (const float*)d_in[10];
    const float* ln1g = (const float*)d_in[11];
    const float* ln1b = (const float*)d_in[12];
    const float* ng = (const float*)d_in[13];
    const float* nb = (const float*)d_in[14];
    const float* linW = (const float*)d_in[15];
    const float* linb = (const float*)d_in[16];
    float* out = (float*)d_out;

    cudaFuncSetAttribute(node_mlp_kernel,
                         cudaFuncAttributeMaxDynamicSharedMemorySize, 65536);

    float *px0, *px1, *px2;
    cudaGetSymbolAddress((void**)&px0, g_x0);
    cudaGetSymbolAddress((void**)&px1, g_x1);
    cudaGetSymbolAddress((void**)&px2, g_x2);

    encoder_kernel<<<1568, 256>>>(x, encW, encb, px0);

    const int edge_blocks = (EE * 16 + 255) / 256;

    // conv 1
    zero_acc_kernel<<<2048, 256>>>();
    edge_pass_kernel<<<edge_blocks, 256>>>(px0, ei, tp);
    node_mlp_kernel<<<444, 128, 65536>>>(px0, px1, W1, b1, g1, be1, W2, b2);

    // conv 2 (shared weights)
    zero_acc_kernel<<<2048, 256>>>();
    edge_pass_kernel<<<edge_blocks, 256>>>(px1, ei, tp);
    node_mlp_kernel<<<444, 128, 65536>>>(px1, px2, W1, b1, g1, be1, W2, b2);

    final_kernel<<<(NN * 32 + 255) / 256, 256>>>(ln1g, ln1b, ng, nb, linW,
                                                 linb, out);
}

// round 4
// speedup vs baseline: 1.3492x; 1.3492x over previous
#include <cuda_runtime.h>

#define NN 50000
#define EE 800000
#define FIN 128
#define HH 64
#define H2 128
#define MSG_EPS 1e-7f
#define NB 8           // nodes per block tile in node_mlp
#define S1 68          // W1T row stride (words), odd bank phase
#define S2 132         // W2T row stride (words), odd bank phase

// Scratch (device globals; no allocation allowed)
__device__ __align__(16) float g_x0[NN * HH];
__device__ __align__(16) float g_x1[NN * HH];
__device__ __align__(16) float g_x2[NN * HH];
__device__ __align__(16) float g_acc[NN * 2 * HH];  // [n][0:64]=denom, [64:128]=numer

__global__ void zero_acc_kernel() {
    int i = blockIdx.x * blockDim.x + threadIdx.x;
    const int total = NN * 2 * HH / 4;
    float4 z = make_float4(0.f, 0.f, 0.f, 0.f);
    for (; i < total; i += gridDim.x * blockDim.x)
        ((float4*)g_acc)[i] = z;
}

// ---------------------------------------------------------------------------
// Encoder: x[N,128] @ W[128,64] + b -> out[N,64]. W resident in smem.
__global__ __launch_bounds__(256) void encoder_kernel(
    const float* __restrict__ x, const float* __restrict__ W,
    const float* __restrict__ b, float* __restrict__ out) {
    __shared__ float Ws[FIN * HH];
    __shared__ float xs[4 * FIN];
    int t = threadIdx.x;
    for (int i = t; i < FIN * HH; i += 256) Ws[i] = W[i];
    float bh = b[t & 63];
    __syncthreads();
    for (int n0 = blockIdx.x * 4; n0 < NN; n0 += gridDim.x * 4) {
        for (int i = t; i < 4 * FIN; i += 256)
            xs[i] = x[(size_t)n0 * FIN + i];
        __syncthreads();
        int node = t >> 6, h = t & 63;
        float acc = bh;
        const float* xr = &xs[node * FIN];
#pragma unroll
        for (int k = 0; k < FIN; k++)
            acc = fmaf(xr[k], Ws[k * HH + h], acc);
        out[(size_t)(n0 + node) * HH + h] = acc;
        __syncthreads();
    }
}

// ---------------------------------------------------------------------------
// Fused edge pass: m = relu(x[src])+eps ; ex = exp(m*t) ;
// red denom[dst] += ex ; red numer[dst] += m*ex. (seg_max eliminated:
// softmax shift-invariant, logits O(1).) Thread = (edge, 4-ch group).
__device__ __forceinline__ void red_add_v4(float* p, float a, float b, float c,
                                           float d) {
    asm volatile("red.global.add.v4.f32 [%0], {%1, %2, %3, %4};" ::"l"(p),
                 "f"(a), "f"(b), "f"(c), "f"(d)
                 : "memory");
}

__global__ __launch_bounds__(256) void edge_pass_kernel(
    const float* __restrict__ xin, const int* __restrict__ ei,
    const float* __restrict__ tp) {
    int idx = blockIdx.x * blockDim.x + threadIdx.x;
    int e = idx >> 4;
    if (e >= EE) return;
    int cg = idx & 15;
    float t = __ldg(tp);
    int s = __ldg(ei + e);
    int d = __ldg(ei + EE + e);
    float4 xv = *(const float4*)(xin + (size_t)s * HH + cg * 4);
    float m0 = fmaxf(xv.x, 0.f) + MSG_EPS;
    float m1 = fmaxf(xv.y, 0.f) + MSG_EPS;
    float m2 = fmaxf(xv.z, 0.f) + MSG_EPS;
    float m3 = fmaxf(xv.w, 0.f) + MSG_EPS;
    float e0 = __expf(m0 * t);
    float e1 = __expf(m1 * t);
    float e2 = __expf(m2 * t);
    float e3 = __expf(m3 * t);
    float* base = g_acc + (size_t)d * (2 * HH);
    red_add_v4(base + cg * 4, e0, e1, e2, e3);
    red_add_v4(base + HH + cg * 4, m0 * e0, m1 * e1, m2 * e2, m3 * e3);
}

// ---------------------------------------------------------------------------
// Node MLP v2: register-tiled, 8 nodes/tile, transposed padded weights,
// LDS.128 weight streaming. row = numer/(denom+eps) + x ;
// h1 = relu(LN(row@W1+b1)) ; out = h1@W2 + b2.
extern __shared__ float smem_dyn[];
__global__ __launch_bounds__(256) void node_mlp_kernel(
    const float* __restrict__ xin, float* __restrict__ xout,
    const float* __restrict__ W1, const float* __restrict__ b1,
    const float* __restrict__ g1, const float* __restrict__ be1,
    const float* __restrict__ W2, const float* __restrict__ b2) {
    float* W1T = smem_dyn;              // [128][S1]  W1T[c][i] = W1[i*128+c]
    float* W2T = smem_dyn + H2 * S1;    // [64][S2]   W2T[c][j] = W2[j*64+c]
    __shared__ float rows[NB * S1];     // [8][S1]
    __shared__ float h1[NB * S2];       // [8][S2]
    __shared__ float b1s[H2], g1s[H2], be1s[H2], b2s[HH];
    __shared__ float mus[NB], rss[NB];
    int t = threadIdx.x;
    for (int idx = t; idx < H2 * HH; idx += 256) {
        int c = idx & 127, i = idx >> 7;
        W1T[c * S1 + i] = W1[i * H2 + c];
        int c2 = idx & 63, j = idx >> 6;
        W2T[c2 * S2 + j] = W2[j * HH + c2];
    }
    if (t < H2) { b1s[t] = b1[t]; g1s[t] = g1[t]; be1s[t] = be1[t]; }
    if (t < HH) b2s[t] = b2[t];
    __syncthreads();

    int cB = t & 127, gB = t >> 7;   // Linear1: channel, node-group (0/1)
    int cC = t & 63, gC = t >> 6;    // Linear2: channel, node-pair (0..3)
    int nodeS = t >> 5, laneS = t & 31;  // stats mapping

    for (int tile = blockIdx.x; tile < NN / NB; tile += gridDim.x) {
        int n0 = tile * NB;
        // Phase A: build 8 node rows (agg-normalize + root add)
        for (int idx = t; idx < NB * HH; idx += 256) {
            int n = idx >> 6, i = idx & 63;
            size_t gi = (size_t)(n0 + n) * (2 * HH);
            float den = g_acc[gi + i];
            float num = g_acc[gi + HH + i];
            rows[n * S1 + i] =
                num / (den + 1e-16f) + xin[(size_t)(n0 + n) * HH + i];
        }
        __syncthreads();
        // Phase B: Linear 64->128, 4 nodes x 1 channel per thread
        float acc[4];
#pragma unroll
        for (int k = 0; k < 4; k++) acc[k] = b1s[cB];
        const float* wr = &W1T[cB * S1];
#pragma unroll
        for (int i4 = 0; i4 < HH; i4 += 4) {
            float4 w = *(const float4*)(wr + i4);
#pragma unroll
            for (int k = 0; k < 4; k++) {
                float4 r = *(const float4*)(&rows[(gB + 2 * k) * S1 + i4]);
                acc[k] = fmaf(r.x, w.x,
                         fmaf(r.y, w.y, fmaf(r.z, w.z, fmaf(r.w, w.w, acc[k]))));
            }
        }
#pragma unroll
        for (int k = 0; k < 4; k++) h1[(gB + 2 * k) * S2 + cB] = acc[k];
        __syncthreads();
        // LN stats: warp-chunk per node (8 nodes x 32 lanes)
        {
            float v0 = h1[nodeS * S2 + laneS];
            float v1 = h1[nodeS * S2 + laneS + 32];
            float v2 = h1[nodeS * S2 + laneS + 64];
            float v3 = h1[nodeS * S2 + laneS + 96];
            float s1 = v0 + v1 + v2 + v3;
            float s2 = v0 * v0 + v1 * v1 + v2 * v2 + v3 * v3;
#pragma unroll
            for (int o = 16; o; o >>= 1) {
                s1 += __shfl_xor_sync(0xffffffffu, s1, o);
                s2 += __shfl_xor_sync(0xffffffffu, s2, o);
            }
            if (laneS == 0) {
                float mu = s1 * (1.f / H2);
                float var = s2 * (1.f / H2) - mu * mu;
                mus[nodeS] = mu;
                rss[nodeS] = rsqrtf(var + 1e-5f);
            }
        }
        __syncthreads();
        // Normalize + ReLU (raw values still in regs)
#pragma unroll
        for (int k = 0; k < 4; k++) {
            int n = gB + 2 * k;
            float hn = (acc[k] - mus[n]) * rss[n] * g1s[cB] + be1s[cB];
            h1[n * S2 + cB] = fmaxf(hn, 0.f);
        }
        __syncthreads();
        // Phase C: Linear 128->64, 2 nodes x 1 channel per thread
        float a0 = b2s[cC], a1 = b2s[cC];
        const float* w2r = &W2T[cC * S2];
        const float* hp = &h1[(2 * gC) * S2];
        const float* hq = &h1[(2 * gC + 1) * S2];
#pragma unroll
        for (int j4 = 0; j4 < H2; j4 += 4) {
            float4 w = *(const float4*)(w2r + j4);
            float4 p = *(const float4*)(hp + j4);
            float4 q = *(const float4*)(hq + j4);
            a0 = fmaf(p.x, w.x, fmaf(p.y, w.y, fmaf(p.z, w.z, fmaf(p.w, w.w, a0))));
            a1 = fmaf(q.x, w.x, fmaf(q.y, w.y, fmaf(q.z, w.z, fmaf(q.w, w.w, a1))));
        }
        xout[(size_t)(n0 + 2 * gC) * HH + cC] = a0;
        xout[(size_t)(n0 + 2 * gC + 1) * HH + cC] = a1;
        // no trailing sync needed: next Phase A writes rows only (previous
        // readers of rows passed the post-B barrier); h1 rewrite of next tile
        // is ordered by the post-A barrier.
    }
}

// ---------------------------------------------------------------------------
// Epilogue: h = relu(LN64(x2)) ; z = relu(LN128([x1,h])) ; out = z@lin_W+lin_b
__global__ __launch_bounds__(256) void final_kernel(
    const float* __restrict__ ln1g, const float* __restrict__ ln1b,
    const float* __restrict__ ng, const float* __restrict__ nb,
    const float* __restrict__ linW, const float* __restrict__ linb,
    float* __restrict__ out) {
    int gw = (blockIdx.x * blockDim.x + threadIdx.x) >> 5;
    int lane = threadIdx.x & 31;
    int nwarps = (gridDim.x * blockDim.x) >> 5;
    for (int n = gw; n < NN; n += nwarps) {
        float a0 = g_x2[(size_t)n * HH + lane];
        float a1 = g_x2[(size_t)n * HH + lane + 32];
        float s1 = a0 + a1, s2 = a0 * a0 + a1 * a1;
#pragma unroll
        for (int o = 16; o; o >>= 1) {
            s1 += __shfl_xor_sync(0xffffffffu, s1, o);
            s2 += __shfl_xor_sync(0xffffffffu, s2, o);
        }
        float mu = s1 * (1.f / 64), var = s2 * (1.f / 64) - mu * mu;
        float rs = rsqrtf(var + 1e-5f);
        float h0 = fmaxf((a0 - mu) * rs * ln1g[lane] + ln1b[lane], 0.f);
        float h1v = fmaxf((a1 - mu) * rs * ln1g[lane + 32] + ln1b[lane + 32], 0.f);
        float c0 = g_x1[(size_t)n * HH + lane];
        float c1 = g_x1[(size_t)n * HH + lane + 32];
        float S1r = c0 + c1 + h0 + h1v;
        float S2r = c0 * c0 + c1 * c1 + h0 * h0 + h1v * h1v;
#pragma unroll
        for (int o = 16; o; o >>= 1) {
            S1r += __shfl_xor_sync(0xffffffffu, S1r, o);
            S2r += __shfl_xor_sync(0xffffffffu, S2r, o);
        }
        float mu2 = S1r * (1.f / 128), var2 = S2r * (1.f / 128) - mu2 * mu2;
        float rs2 = rsqrtf(var2 + 1e-5f);
        float z0 = fmaxf((c0 - mu2) * rs2 * ng[lane] + nb[lane], 0.f);
        float z1 = fmaxf((c1 - mu2) * rs2 * ng[lane + 32] + nb[lane + 32], 0.f);
        float z2 = fmaxf((h0 - mu2) * rs2 * ng[64 + lane] + nb[64 + lane], 0.f);
        float z3 = fmaxf((h1v - mu2) * rs2 * ng[96 + lane] + nb[96 + lane], 0.f);
        float dot = z0 * linW[lane] + z1 * linW[lane + 32] +
                    z2 * linW[64 + lane] + z3 * linW[96 + lane];
#pragma unroll
        for (int o = 16; o; o >>= 1)
            dot += __shfl_xor_sync(0xffffffffu, dot, o);
        if (lane == 0) out[n] = dot + linb[0];
    }
}

// ---------------------------------------------------------------------------
extern "C" void kernel_launch(void* const* d_in, const int* in_sizes, int n_in,
                              void* d_out, int out_size) {
    const float* x = (const float*)d_in[0];
    const int* ei = (const int*)d_in[1];  // int32 (JAX x64-disabled)
    const float* encW = (const float*)d_in[2];
    const float* encb = (const float*)d_in[3];
    const float* tp = (const float*)d_in[4];
    const float* W1 = (const float*)d_in[5];
    const float* b1 = (const float*)d_in[6];
    const float* g1 = (const float*)d_in[7];
    const float* be1 = (const float*)d_in[8];
    const float* W2 = (const float*)d_in[9];
    const float* b2 = (const float*)d_in[10];
    const float* ln1g = (const float*)d_in[11];
    const float* ln1b = (const float*)d_in[12];
    const float* ng = (const float*)d_in[13];
    const float* nb = (const float*)d_in[14];
    const float* linW = (const float*)d_in[15];
    const float* linb = (const float*)d_in[16];
    float* out = (float*)d_out;

    const int dyn_smem = (H2 * S1 + HH * S2) * 4;  // 68608 B
    cudaFuncSetAttribute(node_mlp_kernel,
                         cudaFuncAttributeMaxDynamicSharedMemorySize, dyn_smem);

    float *px0, *px1, *px2;
    cudaGetSymbolAddress((void**)&px0, g_x0);
    cudaGetSymbolAddress((void**)&px1, g_x1);
    cudaGetSymbolAddress((void**)&px2, g_x2);

    encoder_kernel<<<1568, 256>>>(x, encW, encb, px0);

    const int edge_blocks = (EE * 16 + 255) / 256;

    // conv 1
    zero_acc_kernel<<<2048, 256>>>();
    edge_pass_kernel<<<edge_blocks, 256>>>(px0, ei, tp);
    node_mlp_kernel<<<296, 256, dyn_smem>>>(px0, px1, W1, b1, g1, be1, W2, b2);

    // conv 2 (shared weights)
    zero_acc_kernel<<<2048, 256>>>();
    edge_pass_kernel<<<edge_blocks, 256>>>(px1, ei, tp);
    node_mlp_kernel<<<296, 256, dyn_smem>>>(px1, px2, W1, b1, g1, be1, W2, b2);

    final_kernel<<<(NN * 32 + 255) / 256, 256>>>(ln1g, ln1b, ng, nb, linW,
                                                 linb, out);
}

// round 8
// speedup vs baseline: 1.5956x; 1.1826x over previous
#include <cuda_runtime.h>

#define NN 50000
#define EE 800000
#define FIN 128
#define HH 64
#define H2 128
#define MSG_EPS 1e-7f
#define NB 16          // nodes per block tile in node_mlp
#define S1 68          // rows/W1T row stride (words): 8-lane phase hits distinct banks
#define S2 132         // h1/W2T row stride (words)

// Scratch (device globals; no allocation allowed)
__device__ __align__(16) float g_x0[NN * HH];
__device__ __align__(16) float g_x1[NN * HH];
__device__ __align__(16) float g_x2[NN * HH];
__device__ __align__(16) float g_acc[NN * 2 * HH];  // [n][0:64]=denom, [64:128]=numer

__global__ void zero_acc_kernel() {
    int i = blockIdx.x * blockDim.x + threadIdx.x;
    const int total = NN * 2 * HH / 4;
    float4 z = make_float4(0.f, 0.f, 0.f, 0.f);
    for (; i < total; i += gridDim.x * blockDim.x)
        ((float4*)g_acc)[i] = z;
}

// ---------------------------------------------------------------------------
// Encoder: x[N,128] @ W[128,64] + b -> out[N,64]. W resident in smem.
__global__ __launch_bounds__(256) void encoder_kernel(
    const float* __restrict__ x, const float* __restrict__ W,
    const float* __restrict__ b, float* __restrict__ out) {
    __shared__ float Ws[FIN * HH];
    __shared__ float xs[4 * FIN];
    int t = threadIdx.x;
    for (int i = t; i < FIN * HH; i += 256) Ws[i] = W[i];
    float bh = b[t & 63];
    __syncthreads();
    for (int n0 = blockIdx.x * 4; n0 < NN; n0 += gridDim.x * 4) {
        for (int i = t; i < 4 * FIN; i += 256)
            xs[i] = x[(size_t)n0 * FIN + i];
        __syncthreads();
        int node = t >> 6, h = t & 63;
        float acc = bh;
        const float* xr = &xs[node * FIN];
#pragma unroll
        for (int k = 0; k < FIN; k++)
            acc = fmaf(xr[k], Ws[k * HH + h], acc);
        out[(size_t)(n0 + node) * HH + h] = acc;
        __syncthreads();
    }
}

// ---------------------------------------------------------------------------
// Fused edge pass: m = relu(x[src])+eps ; ex = exp(m*t) ;
// red denom[dst] += ex ; red numer[dst] += m*ex. (seg_max eliminated:
// softmax shift-invariant, logits O(1).) Thread = (edge, 4-ch group).
__device__ __forceinline__ void red_add_v4(float* p, float a, float b, float c,
                                           float d) {
    asm volatile("red.global.add.v4.f32 [%0], {%1, %2, %3, %4};" ::"l"(p),
                 "f"(a), "f"(b), "f"(c), "f"(d)
                 : "memory");
}

__global__ __launch_bounds__(256) void edge_pass_kernel(
    const float* __restrict__ xin, const int* __restrict__ ei,
    const float* __restrict__ tp) {
    int idx = blockIdx.x * blockDim.x + threadIdx.x;
    int e = idx >> 4;
    if (e >= EE) return;
    int cg = idx & 15;
    float t = __ldg(tp);
    int s = __ldg(ei + e);
    int d = __ldg(ei + EE + e);
    float4 xv = *(const float4*)(xin + (size_t)s * HH + cg * 4);
    float m0 = fmaxf(xv.x, 0.f) + MSG_EPS;
    float m1 = fmaxf(xv.y, 0.f) + MSG_EPS;
    float m2 = fmaxf(xv.z, 0.f) + MSG_EPS;
    float m3 = fmaxf(xv.w, 0.f) + MSG_EPS;
    float e0 = __expf(m0 * t);
    float e1 = __expf(m1 * t);
    float e2 = __expf(m2 * t);
    float e3 = __expf(m3 * t);
    float* base = g_acc + (size_t)d * (2 * HH);
    red_add_v4(base + cg * 4, e0, e1, e2, e3);
    red_add_v4(base + HH + cg * 4, m0 * e0, m1 * e1, m2 * e2, m3 * e3);
}

// ---------------------------------------------------------------------------
// Node MLP v3: 16 nodes/tile, 8 outputs/thread register tiles.
// row = numer/(denom+eps)+x ; h1 = relu(LN(row@W1+b1)) ; out = h1@W2+b2.
extern __shared__ float smem_dyn[];
__global__ __launch_bounds__(256) void node_mlp_kernel(
    const float* __restrict__ xin, float* __restrict__ xout,
    const float* __restrict__ W1, const float* __restrict__ b1,
    const float* __restrict__ g1, const float* __restrict__ be1,
    const float* __restrict__ W2, const float* __restrict__ b2) {
    float* W1T = smem_dyn;            // [128][S1]  W1T[c][i] = W1[i*128+c]
    float* W2T = smem_dyn + H2 * S1;  // [64][S2]   W2T[c][j] = W2[j*64+c]
    __shared__ float rows[NB * S1];   // [16][S1]
    __shared__ float h1[NB * S2];     // [16][S2]
    __shared__ float b1s[H2], g1s[H2], be1s[H2], b2s[HH];
    __shared__ float mus[NB], rss[NB];
    int t = threadIdx.x;
    for (int idx = t; idx < H2 * HH; idx += 256) {
        int c = idx & 127, i = idx >> 7;
        W1T[c * S1 + i] = W1[i * H2 + c];
        int c2 = idx & 63, j = idx >> 6;
        W2T[c2 * S2 + j] = W2[j * HH + c2];
    }
    if (t < H2) { b1s[t] = b1[t]; g1s[t] = g1[t]; be1s[t] = be1[t]; }
    if (t < HH) b2s[t] = b2[t];
    __syncthreads();

    const int nA = t >> 4, cgA = t & 15;  // Phase A: node, 4-ch group
    const int cB = t & 63, gB = t >> 6;   // Phase B: ch pair (cB, cB+64), node grp (4)
    const int cC = t & 31, gC = t >> 5;   // Phase C: ch pair (cC, cC+32), node pair
    const int wS = t >> 5, lS = t & 31;   // stats: warp -> nodes (2wS, 2wS+1)

    for (int tile = blockIdx.x; tile < NN / NB; tile += gridDim.x) {
        int n0 = tile * NB;
        // --- Phase A: build 16 node rows (agg-normalize + root add), vec4
        {
            size_t gi = (size_t)(n0 + nA) * (2 * HH) + cgA * 4;
            float4 den = *(const float4*)(g_acc + gi);
            float4 num = *(const float4*)(g_acc + gi + HH);
            float4 xv =
                *(const float4*)(xin + (size_t)(n0 + nA) * HH + cgA * 4);
            float4 r;
            r.x = num.x / (den.x + 1e-16f) + xv.x;
            r.y = num.y / (den.y + 1e-16f) + xv.y;
            r.z = num.z / (den.z + 1e-16f) + xv.z;
            r.w = num.w / (den.w + 1e-16f) + xv.w;
            *(float4*)(&rows[nA * S1 + cgA * 4]) = r;
        }
        __syncthreads();
        // --- Phase B: Linear 64->128, 4 nodes x 2 channels per thread
        float acc[8];
#pragma unroll
        for (int k = 0; k < 4; k++) { acc[k] = b1s[cB]; acc[4 + k] = b1s[cB + 64]; }
        const float* w0p = &W1T[cB * S1];
        const float* w1p = &W1T[(cB + 64) * S1];
#pragma unroll
        for (int i4 = 0; i4 < HH; i4 += 4) {
            float4 w0 = *(const float4*)(w0p + i4);
            float4 w1 = *(const float4*)(w1p + i4);
#pragma unroll
            for (int k = 0; k < 4; k++) {
                float4 r = *(const float4*)(&rows[(gB * 4 + k) * S1 + i4]);
                acc[k] = fmaf(r.x, w0.x,
                         fmaf(r.y, w0.y, fmaf(r.z, w0.z, fmaf(r.w, w0.w, acc[k]))));
                acc[4 + k] = fmaf(r.x, w1.x,
                             fmaf(r.y, w1.y,
                                  fmaf(r.z, w1.z, fmaf(r.w, w1.w, acc[4 + k]))));
            }
        }
#pragma unroll
        for (int k = 0; k < 4; k++) {
            int n = gB * 4 + k;
            h1[n * S2 + cB] = acc[k];
            h1[n * S2 + cB + 64] = acc[4 + k];
        }
        __syncthreads();
        // --- LN stats: warp wS handles nodes 2wS, 2wS+1
        {
            float sa1 = 0.f, sa2 = 0.f, sb1 = 0.f, sb2 = 0.f;
#pragma unroll
            for (int k = 0; k < 4; k++) {
                float va = h1[(2 * wS) * S2 + lS + 32 * k];
                float vb = h1[(2 * wS + 1) * S2 + lS + 32 * k];
                sa1 += va; sa2 += va * va;
                sb1 += vb; sb2 += vb * vb;
            }
#pragma unroll
            for (int o = 16; o; o >>= 1) {
                sa1 += __shfl_xor_sync(0xffffffffu, sa1, o);
                sa2 += __shfl_xor_sync(0xffffffffu, sa2, o);
                sb1 += __shfl_xor_sync(0xffffffffu, sb1, o);
                sb2 += __shfl_xor_sync(0xffffffffu, sb2, o);
            }
            if (lS == 0) {
                float mu = sa1 * (1.f / H2);
                float var = sa2 * (1.f / H2) - mu * mu;
                mus[2 * wS] = mu;
                rss[2 * wS] = rsqrtf(var + 1e-5f);
                mu = sb1 * (1.f / H2);
                var = sb2 * (1.f / H2) - mu * mu;
                mus[2 * wS + 1] = mu;
                rss[2 * wS + 1] = rsqrtf(var + 1e-5f);
            }
        }
        __syncthreads();
        // --- Normalize + ReLU (raw accs still in registers)
        {
            float ga = g1s[cB], ba = be1s[cB];
            float gb = g1s[cB + 64], bb = be1s[cB + 64];
#pragma unroll
            for (int k = 0; k < 4; k++) {
                int n = gB * 4 + k;
                float mu = mus[n], rs = rss[n];
                h1[n * S2 + cB] = fmaxf((acc[k] - mu) * rs * ga + ba, 0.f);
                h1[n * S2 + cB + 64] =
                    fmaxf((acc[4 + k] - mu) * rs * gb + bb, 0.f);
            }
        }
        __syncthreads();
        // --- Phase C: Linear 128->64, 2 nodes x 2 channels per thread
        float a00 = b2s[cC], a01 = b2s[cC + 32];
        float a10 = b2s[cC], a11 = b2s[cC + 32];
        const float* w2a = &W2T[cC * S2];
        const float* w2b = &W2T[(cC + 32) * S2];
        const float* hp = &h1[(2 * gC) * S2];
        const float* hq = &h1[(2 * gC + 1) * S2];
#pragma unroll
        for (int j4 = 0; j4 < H2; j4 += 4) {
            float4 wa = *(const float4*)(w2a + j4);
            float4 wb = *(const float4*)(w2b + j4);
            float4 p = *(const float4*)(hp + j4);
            float4 q = *(const float4*)(hq + j4);
            a00 = fmaf(p.x, wa.x, fmaf(p.y, wa.y, fmaf(p.z, wa.z, fmaf(p.w, wa.w, a00))));
            a01 = fmaf(p.x, wb.x, fmaf(p.y, wb.y, fmaf(p.z, wb.z, fmaf(p.w, wb.w, a01))));
            a10 = fmaf(q.x, wa.x, fmaf(q.y, wa.y, fmaf(q.z, wa.z, fmaf(q.w, wa.w, a10))));
            a11 = fmaf(q.x, wb.x, fmaf(q.y, wb.y, fmaf(q.z, wb.z, fmaf(q.w, wb.w, a11))));
        }
        xout[(size_t)(n0 + 2 * gC) * HH + cC] = a00;
        xout[(size_t)(n0 + 2 * gC) * HH + cC + 32] = a01;
        xout[(size_t)(n0 + 2 * gC + 1) * HH + cC] = a10;
        xout[(size_t)(n0 + 2 * gC + 1) * HH + cC + 32] = a11;
        // Safe hazard note: next Phase A writes rows[] only; every other thread
        // has passed the post-B barrier (rows' last readers) before re-entering
        // A via its trailing barrier. h1 rewrites are fenced by post-A barrier.
    }
}

// ---------------------------------------------------------------------------
// Epilogue: h = relu(LN64(x2)) ; z = relu(LN128([x1,h])) ; out = z@lin_W+lin_b
__global__ __launch_bounds__(256) void final_kernel(
    const float* __restrict__ ln1g, const float* __restrict__ ln1b,
    const float* __restrict__ ng, const float* __restrict__ nb,
    const float* __restrict__ linW, const float* __restrict__ linb,
    float* __restrict__ out) {
    int gw = (blockIdx.x * blockDim.x + threadIdx.x) >> 5;
    int lane = threadIdx.x & 31;
    int nwarps = (gridDim.x * blockDim.x) >> 5;
    for (int n = gw; n < NN; n += nwarps) {
        float a0 = g_x2[(size_t)n * HH + lane];
        float a1 = g_x2[(size_t)n * HH + lane + 32];
        float s1 = a0 + a1, s2 = a0 * a0 + a1 * a1;
#pragma unroll
        for (int o = 16; o; o >>= 1) {
            s1 += __shfl_xor_sync(0xffffffffu, s1, o);
            s2 += __shfl_xor_sync(0xffffffffu, s2, o);
        }
        float mu = s1 * (1.f / 64), var = s2 * (1.f / 64) - mu * mu;
        float rs = rsqrtf(var + 1e-5f);
        float h0 = fmaxf((a0 - mu) * rs * ln1g[lane] + ln1b[lane], 0.f);
        float h1v = fmaxf((a1 - mu) * rs * ln1g[lane + 32] + ln1b[lane + 32], 0.f);
        float c0 = g_x1[(size_t)n * HH + lane];
        float c1 = g_x1[(size_t)n * HH + lane + 32];
        float S1r = c0 + c1 + h0 + h1v;
        float S2r = c0 * c0 + c1 * c1 + h0 * h0 + h1v * h1v;
#pragma unroll
        for (int o = 16; o; o >>= 1) {
            S1r += __shfl_xor_sync(0xffffffffu, S1r, o);
            S2r += __shfl_xor_sync(0xffffffffu, S2r, o);
        }
        float mu2 = S1r * (1.f / 128), var2 = S2r * (1.f / 128) - mu2 * mu2;
        float rs2 = rsqrtf(var2 + 1e-5f);
        float z0 = fmaxf((c0 - mu2) * rs2 * ng[lane] + nb[lane], 0.f);
        float z1 = fmaxf((c1 - mu2) * rs2 * ng[lane + 32] + nb[lane + 32], 0.f);
        float z2 = fmaxf((h0 - mu2) * rs2 * ng[64 + lane] + nb[64 + lane], 0.f);
        float z3 = fmaxf((h1v - mu2) * rs2 * ng[96 + lane] + nb[96 + lane], 0.f);
        float dot = z0 * linW[lane] + z1 * linW[lane + 32] +
                    z2 * linW[64 + lane] + z3 * linW[96 + lane];
#pragma unroll
        for (int o = 16; o; o >>= 1)
            dot += __shfl_xor_sync(0xffffffffu, dot, o);
        if (lane == 0) out[n] = dot + linb[0];
    }
}

// ---------------------------------------------------------------------------
extern "C" void kernel_launch(void* const* d_in, const int* in_sizes, int n_in,
                              void* d_out, int out_size) {
    const float* x = (const float*)d_in[0];
    const int* ei = (const int*)d_in[1];  // int32 (JAX x64-disabled)
    const float* encW = (const float*)d_in[2];
    const float* encb = (const float*)d_in[3];
    const float* tp = (const float*)d_in[4];
    const float* W1 = (const float*)d_in[5];
    const float* b1 = (const float*)d_in[6];
    const float* g1 = (const float*)d_in[7];
    const float* be1 = (const float*)d_in[8];
    const float* W2 = (const float*)d_in[9];
    const float* b2 = (const float*)d_in[10];
    const float* ln1g = (const float*)d_in[11];
    const float* ln1b = (const float*)d_in[12];
    const float* ng = (const float*)d_in[13];
    const float* nb = (const float*)d_in[14];
    const float* linW = (const float*)d_in[15];
    const float* linb = (const float*)d_in[16];
    float* out = (float*)d_out;

    const int dyn_smem = (H2 * S1 + HH * S2) * 4;  // 68608 B
    cudaFuncSetAttribute(node_mlp_kernel,
                         cudaFuncAttributeMaxDynamicSharedMemorySize, dyn_smem);

    float *px0, *px1, *px2;
    cudaGetSymbolAddress((void**)&px0, g_x0);
    cudaGetSymbolAddress((void**)&px1, g_x1);
    cudaGetSymbolAddress((void**)&px2, g_x2);

    encoder_kernel<<<1568, 256>>>(x, encW, encb, px0);

    const int edge_blocks = (EE * 16 + 255) / 256;

    // conv 1
    zero_acc_kernel<<<2048, 256>>>();
    edge_pass_kernel<<<edge_blocks, 256>>>(px0, ei, tp);
    node_mlp_kernel<<<296, 256, dyn_smem>>>(px0, px1, W1, b1, g1, be1, W2, b2);

    // conv 2 (shared weights)
    zero_acc_kernel<<<2048, 256>>>();
    edge_pass_kernel<<<edge_blocks, 256>>>(px1, ei, tp);
    node_mlp_kernel<<<296, 256, dyn_smem>>>(px1, px2, W1, b1, g1, be1, W2, b2);

    final_kernel<<<(NN * 32 + 255) / 256, 256>>>(ln1g, ln1b, ng, nb, linW,
                                                 linb, out);
}